// round 2
// baseline (speedup 1.0000x reference)
#include <cuda_runtime.h>

// Problem constants
#define BB 4096
#define DD 1024
#define RR 256
#define TM 32                 // batch rows per CTA
#define NCTA (BB / TM)        // 128
#define NTHR 256
#define SHP 257               // padded row stride for tiles (conflict-free transpose)

// Yoshida-4 coefficients (double-precision literals, truncated to float at use)
#define K_W1 1.3512071919596578
#define K_W0 (-1.7024143839193153)
#define K_C1 ((float)(K_W1 * 0.5))                 // = C4
#define K_C2 ((float)((K_W0 + K_W1) * 0.5))        // = C3
#define K_DT 0.01f

__global__ __launch_bounds__(NTHR, 1)
void yoshida_fused_kernel(const float* __restrict__ x,
                          const float* __restrict__ v,
                          const float* __restrict__ force,
                          const float* __restrict__ U,   // [R][D]
                          const float* __restrict__ W,   // [D][R]
                          float* __restrict__ out)       // [2][B][D]: x_final then v3
{
    extern __shared__ float smem[];
    float* sv = smem;                    // [TM][D]      v tile (master copy, fp32)
    float* sh = sv + TM * DD;            // [TM][SHP]    h^2 tile
    float* st = sh + TM * SHP;           // [32][SHP]    U/W staging tile (transposed)

    const int tid  = threadIdx.x;
    const int row0 = blockIdx.x * TM;

    const int bq = tid >> 5;     // 0..7  (4 batch rows each)  -- warp-uniform
    const int lq = tid & 31;     // 0..31 (r or d lane index)

    // ---- load v tile (coalesced float4) ----
    {
        const float4* vsrc = (const float4*)(v + (size_t)row0 * DD);
        float4* dst = (float4*)sv;
        #pragma unroll 4
        for (int i = tid; i < TM * DD / 4; i += NTHR) dst[i] = vsrc[i];
    }
    __syncthreads();

    const float dcoef_tab[3] = { (float)K_W1 * K_DT, (float)K_W0 * K_DT, (float)K_W1 * K_DT };

    for (int step = 0; step < 3; ++step) {
        // ================= Stage 1: h[b][r] = sum_d U[r][d] * sv[b][d]; sh = h*h ====
        float acc[4][8];
        #pragma unroll
        for (int j = 0; j < 4; ++j)
            #pragma unroll
            for (int i = 0; i < 8; ++i) acc[j][i] = 0.f;

        for (int kt = 0; kt < DD / 32; ++kt) {
            // load U[0:256][kt*32 .. +32] -> st[d_local][r] (transposed, padded)
            {
                const int f4 = tid & 7;       // which float4 of the 32-wide d chunk
                const int rr = tid >> 3;      // base row
                #pragma unroll
                for (int it = 0; it < 8; ++it) {
                    const int r = rr + 32 * it;
                    float4 g = *(const float4*)(U + (size_t)r * DD + kt * 32 + f4 * 4);
                    st[(f4 * 4 + 0) * SHP + r] = g.x;
                    st[(f4 * 4 + 1) * SHP + r] = g.y;
                    st[(f4 * 4 + 2) * SHP + r] = g.z;
                    st[(f4 * 4 + 3) * SHP + r] = g.w;
                }
            }
            __syncthreads();

            const float* svb = sv + (bq * 4) * DD + kt * 32;
            #pragma unroll
            for (int dd2 = 0; dd2 < 32; ++dd2) {
                const float a0 = svb[0 * DD + dd2];
                const float a1 = svb[1 * DD + dd2];
                const float a2 = svb[2 * DD + dd2];
                const float a3 = svb[3 * DD + dd2];
                const float* str = st + dd2 * SHP + lq;
                #pragma unroll
                for (int i = 0; i < 8; ++i) {
                    const float u = str[32 * i];
                    acc[0][i] += a0 * u;
                    acc[1][i] += a1 * u;
                    acc[2][i] += a2 * u;
                    acc[3][i] += a3 * u;
                }
            }
            __syncthreads();
        }
        // write h^2
        #pragma unroll
        for (int j = 0; j < 4; ++j)
            #pragma unroll
            for (int i = 0; i < 8; ++i)
                sh[(bq * 4 + j) * SHP + lq + 32 * i] = acc[j][i] * acc[j][i];
        __syncthreads();

        // ===== Stage 2: Gamma[b][d] = sum_r W[d][r] * sh[b][r], fused v/x update ====
        const float dcoef = dcoef_tab[step];

        for (int nt = 0; nt < 4; ++nt) {       // d-tile of 256
            float acc2[4][8];
            #pragma unroll
            for (int j = 0; j < 4; ++j)
                #pragma unroll
                for (int i = 0; i < 8; ++i) acc2[j][i] = 0.f;

            for (int rt = 0; rt < 8; ++rt) {   // r-tile of 32
                // load W[nt*256 .. +256][rt*32 .. +32] -> st[r_local][d_local]
                {
                    const int f4 = tid & 7;
                    const int dl0 = tid >> 3;
                    #pragma unroll
                    for (int it = 0; it < 8; ++it) {
                        const int dl = dl0 + 32 * it;
                        float4 g = *(const float4*)(W + (size_t)(nt * 256 + dl) * RR + rt * 32 + f4 * 4);
                        st[(f4 * 4 + 0) * SHP + dl] = g.x;
                        st[(f4 * 4 + 1) * SHP + dl] = g.y;
                        st[(f4 * 4 + 2) * SHP + dl] = g.z;
                        st[(f4 * 4 + 3) * SHP + dl] = g.w;
                    }
                }
                __syncthreads();

                const float* shb = sh + (bq * 4) * SHP + rt * 32;
                #pragma unroll
                for (int rr2 = 0; rr2 < 32; ++rr2) {
                    const float a0 = shb[0 * SHP + rr2];
                    const float a1 = shb[1 * SHP + rr2];
                    const float a2 = shb[2 * SHP + rr2];
                    const float a3 = shb[3 * SHP + rr2];
                    const float* str = st + rr2 * SHP + lq;
                    #pragma unroll
                    for (int i = 0; i < 8; ++i) {
                        const float w = str[32 * i];
                        acc2[0][i] += a0 * w;
                        acc2[1][i] += a1 * w;
                        acc2[2][i] += a2 * w;
                        acc2[3][i] += a3 * w;
                    }
                }
                __syncthreads();
            }

            // elementwise update: v += dcoef * (force - Gamma); fold x accumulation
            #pragma unroll
            for (int j = 0; j < 4; ++j) {
                const int b    = bq * 4 + j;
                const size_t grow = (size_t)(row0 + b) * DD;
                #pragma unroll
                for (int i = 0; i < 8; ++i) {
                    const int d = nt * 256 + lq + 32 * i;
                    const float g    = force[grow + d];
                    const float a    = g - acc2[j][i];
                    const float vold = sv[b * DD + d];
                    const float vnew = vold + dcoef * a;
                    sv[b * DD + d] = vnew;

                    float* ox = out + grow + d;   // x-region used as accumulator
                    if (step == 0) {
                        *ox = K_C1 * vold + K_C2 * vnew;           // C1*v0 + C2*v1
                    } else if (step == 1) {
                        *ox = *ox + K_C2 * vnew;                   // + C3*v2  (C3==C2)
                    } else {
                        const float xa = *ox + K_C1 * vnew;        // + C4*v3  (C4==C1)
                        *ox = x[grow + d] + K_DT * xa;             // x_final
                        out[(size_t)BB * DD + grow + d] = vnew;    // v3
                    }
                }
            }
            __syncthreads();
        }
    }
}

extern "C" void kernel_launch(void* const* d_in, const int* in_sizes, int n_in,
                              void* d_out, int out_size)
{
    const float* x     = (const float*)d_in[0];
    const float* v     = (const float*)d_in[1];
    const float* force = (const float*)d_in[2];
    const float* U     = (const float*)d_in[3];
    const float* W     = (const float*)d_in[4];
    float* out = (float*)d_out;

    const size_t smem_bytes = (size_t)(TM * DD + TM * SHP + 32 * SHP) * sizeof(float);
    cudaFuncSetAttribute(yoshida_fused_kernel,
                         cudaFuncAttributeMaxDynamicSharedMemorySize, (int)smem_bytes);

    yoshida_fused_kernel<<<NCTA, NTHR, smem_bytes>>>(x, v, force, U, W, out);
}

// round 4
// speedup vs baseline: 3.2180x; 3.2180x over previous
#include <cuda_runtime.h>
#include <cuda_bf16.h>
#include <stdint.h>

#define BB 4096
#define DD 1024
#define RR 256
#define NCTA 128
#define NTHR 256

#define K_W1 1.3512071919596578
#define K_W0 (-1.7024143839193153)
#define K_C1f ((float)(K_W1 * 0.5))
#define K_C2f ((float)((K_W0 + K_W1) * 0.5))
#define K_DT 0.01f

// -------- device-global scratch (no runtime allocation) --------
__device__ __align__(1024) unsigned char g_Ub[16 * 32768];                  // U bf16: 16 k-chunks [256n x 64k] SW128
__device__ __align__(1024) unsigned char g_Wb[32 * 16384];                  // W bf16: 8 n-chunks x 4 k-tiles [128n x 64k] SW128
__device__ __align__(1024) unsigned char g_vb[(size_t)NCTA * 16 * 4096];    // v bf16: per-CTA 16 k-chunks [32m x 64k] SW128
__device__ __align__(1024) float g_vf[(size_t)BB * DD];                     // v fp32 master

// -------- helpers --------
__device__ __forceinline__ uint32_t swz(uint32_t o) { return o ^ ((o >> 3) & 0x70); }
__device__ __forceinline__ uint32_t s2u(const void* p) {
    uint32_t a; asm("{ .reg .u64 t; cvta.to.shared.u64 t, %1; cvt.u32.u64 %0, t; }" : "=r"(a) : "l"(p)); return a;
}
__device__ __forceinline__ uint32_t bf2u(__nv_bfloat162 b) { return *reinterpret_cast<uint32_t*>(&b); }
__device__ __forceinline__ void mb_init(uint32_t a, uint32_t c) {
    asm volatile("mbarrier.init.shared.b64 [%0], %1;" :: "r"(a), "r"(c) : "memory");
}
__device__ __forceinline__ void mb_expect(uint32_t a, uint32_t b) {
    asm volatile("mbarrier.arrive.expect_tx.shared.b64 _, [%0], %1;" :: "r"(a), "r"(b) : "memory");
}
__device__ __forceinline__ void mb_wait(uint32_t a, uint32_t p) {
    asm volatile("{\n\t.reg .pred P;\n\tLW%=:\n\t"
        "mbarrier.try_wait.parity.acquire.cta.shared::cta.b64 P, [%0], %1, 0x989680;\n\t"
        "@P bra LD%=;\n\tbra LW%=;\n\tLD%=:\n\t}" :: "r"(a), "r"(p) : "memory");
}
__device__ __forceinline__ void bulkcp(uint32_t d, const void* s, uint32_t n, uint32_t mb) {
    asm volatile("cp.async.bulk.shared::cluster.global.mbarrier::complete_tx::bytes [%0], [%1], %2, [%3];"
                 :: "r"(d), "l"(s), "r"(n), "r"(mb) : "memory");
}
__device__ __forceinline__ void fence_async_sh() { asm volatile("fence.proxy.async.shared::cta;" ::: "memory"); }
__device__ __forceinline__ void fence_async() { asm volatile("fence.proxy.async;" ::: "memory"); }
__device__ __forceinline__ void ldsm4(uint32_t* r, uint32_t a) {
    asm volatile("ldmatrix.sync.aligned.m8n8.x4.shared.b16 {%0,%1,%2,%3}, [%4];"
                 : "=r"(r[0]), "=r"(r[1]), "=r"(r[2]), "=r"(r[3]) : "r"(a));
}
__device__ __forceinline__ void mma16816(float* c, const uint32_t* a, const uint32_t* b) {
    asm volatile("mma.sync.aligned.m16n8k16.row.col.f32.bf16.bf16.f32 "
        "{%0,%1,%2,%3}, {%4,%5,%6,%7}, {%8,%9}, {%0,%1,%2,%3};"
        : "+f"(c[0]), "+f"(c[1]), "+f"(c[2]), "+f"(c[3])
        : "r"(a[0]), "r"(a[1]), "r"(a[2]), "r"(a[3]), "r"(b[0]), "r"(b[1]));
}
__device__ __forceinline__ void sts32(uint32_t a, uint32_t v) {
    asm volatile("st.shared.b32 [%0], %1;" :: "r"(a), "r"(v) : "memory");
}

// -------- prologue: fp32 -> bf16 SW128 tiles in gmem --------
__global__ void prep_uw_kernel(const float* __restrict__ U, const float* __restrict__ W) {
    int idx = blockIdx.x * blockDim.x + threadIdx.x;       // 262144
    if (idx < 131072) {                                    // U: kc(16) x r(256) x j(32 pairs)
        int kc = idx >> 13, rem = idx & 8191, r = rem >> 5, j = rem & 31;
        float2 f = *(const float2*)(U + (size_t)r * DD + kc * 64 + j * 2);
        *(uint32_t*)(g_Ub + kc * 32768 + swz((uint32_t)(r * 128 + j * 4))) = bf2u(__float22bfloat162_rn(f));
    } else {                                               // W: t(32)=nc*4+kt x dr(128) x j(32)
        int i2 = idx - 131072;
        int t = i2 >> 12, rem = i2 & 4095, dr = rem >> 5, j = rem & 31;
        int nc = t >> 2, kt = t & 3;
        float2 f = *(const float2*)(W + (size_t)(nc * 128 + dr) * RR + kt * 64 + j * 2);
        *(uint32_t*)(g_Wb + t * 16384 + swz((uint32_t)(dr * 128 + j * 4))) = bf2u(__float22bfloat162_rn(f));
    }
}
__global__ void prep_v_kernel(const float* __restrict__ v) {
    int idx = blockIdx.x * blockDim.x + threadIdx.x;       // 2097152
    int rg = idx >> 9, j9 = idx & 511, kc = j9 >> 5, j = j9 & 31;
    int cta = rg >> 5, r = rg & 31;
    float2 f = *(const float2*)(v + (size_t)rg * DD + kc * 64 + j * 2);
    *(uint32_t*)(g_vb + (size_t)(cta * 16 + kc) * 4096 + swz((uint32_t)(r * 128 + j * 4))) = bf2u(__float22bfloat162_rn(f));
}

// -------- main fused integrator --------
__global__ __launch_bounds__(NTHR, 1)
void yoshida_mma_kernel(const float* __restrict__ x, const float* __restrict__ v,
                        const float* __restrict__ force, float* __restrict__ out) {
    extern __shared__ unsigned char dsm[];
    unsigned char* basep = (unsigned char*)(((uintptr_t)dsm + 1023u) & ~(uintptr_t)1023u);
    const uint32_t base = s2u(basep);
    const uint32_t BUF = base;                 // 2 x 64KB: GEMM1 buf = [vtile 4K | Uchunk 32K]; GEMM2 = W chunk 64K
    const uint32_t H2  = base + 131072u;       // 4 x 4KB h^2 tiles [32 x 64] bf16 SW128
    float* SGf = (float*)(basep + 147456u);    // sGamma [32][132] f32 (16896B)
    const uint32_t FB0 = base + 164352u, FB1 = base + 164360u;

    const int tid = threadIdx.x, wid = tid >> 5, lid = tid & 31;
    const int mh = wid >> 2;                   // M half (0/1): rows mh*16..+15
    const int q  = wid & 3;                    // N quadrant
    const int row0 = blockIdx.x * 32;

    // ldmatrix per-lane row offsets (byte offsets within tile, pre-swizzle)
    const uint32_t arow = (uint32_t)((mh * 16 + (lid & 15)) * 128 + ((lid >> 4) << 4));
    const uint32_t brow = (uint32_t)(((lid & 7) + ((lid >> 4) << 3)) * 128 + (((lid >> 3) & 1) << 4));
    const int hr = lid >> 2, hc2 = (lid & 3) * 2;

    if (tid == 0) { mb_init(FB0, 1); mb_init(FB1, 1); fence_async_sh(); }
    __syncthreads();

    uint32_t ph0 = 0, ph1 = 0;
    const float dctab[3] = { (float)K_W1 * K_DT, (float)K_W0 * K_DT, (float)K_W1 * K_DT };
    const unsigned char* vbcta = g_vb + (size_t)blockIdx.x * 16 * 4096;
    unsigned char* vbw = g_vb + (size_t)blockIdx.x * 16 * 4096;

    // elementwise mapping (fixed per thread across steps -> no cross-thread v deps)
    const int er = tid >> 3;
    const int el = (tid & 7) * 4;
    const size_t grow = (size_t)(row0 + er) * DD;

    for (int step = 0; step < 3; ++step) {
        const float dcoef = dctab[step];
        const float* vsrc = (step == 0) ? v : g_vf;

        // ---- issue GEMM1 chunks 0,1 ----
        if (tid == 0) {
            fence_async();   // order prior STG (g_vb) before bulk reads
            #pragma unroll
            for (int c = 0; c < 2; ++c) {
                uint32_t fb = c ? FB1 : FB0, sa = BUF + c * 65536u;
                mb_expect(fb, 36864u);
                bulkcp(sa,          vbcta + c * 4096,  4096u,  fb);
                bulkcp(sa + 4096u,  g_Ub  + c * 32768, 32768u, fb);
            }
        }

        // ===== GEMM1: h[32 x 256] = v @ U^T, K=1024 in 16 chunks =====
        float acc1[8][4];
        #pragma unroll
        for (int t = 0; t < 8; ++t)
            #pragma unroll
            for (int j = 0; j < 4; ++j) acc1[t][j] = 0.f;

        for (int kc = 0; kc < 16; ++kc) {
            const int s = kc & 1;
            mb_wait(s ? FB1 : FB0, s ? ph1 : ph0);
            if (s) ph1 ^= 1; else ph0 ^= 1;
            const uint32_t Ab = BUF + (uint32_t)s * 65536u;
            const uint32_t Bb = Ab + 4096u;
            #pragma unroll
            for (int ks = 0; ks < 4; ++ks) {
                uint32_t a[4];
                ldsm4(a, Ab + swz(arow + ks * 32));
                #pragma unroll
                for (int ntp = 0; ntp < 4; ++ntp) {
                    uint32_t b[4];
                    ldsm4(b, Bb + swz(brow + (uint32_t)((q * 64 + ntp * 16) * 128) + ks * 32));
                    mma16816(acc1[2 * ntp],     a, b);
                    mma16816(acc1[2 * ntp + 1], a, b + 2);
                }
            }
            __syncthreads();                 // buffer consumed by all warps
            if (kc + 2 < 16 && tid == 0) {
                uint32_t fb = s ? FB1 : FB0, sa = BUF + (uint32_t)s * 65536u;
                mb_expect(fb, 36864u);
                bulkcp(sa,         vbcta + (kc + 2) * 4096,  4096u,  fb);
                bulkcp(sa + 4096u, g_Ub  + (kc + 2) * 32768, 32768u, fb);
            }
        }

        // ---- h^2 -> bf16 SW128 smem tiles ----
        {
            const uint32_t ht = H2 + (uint32_t)q * 4096u;
            #pragma unroll
            for (int nt = 0; nt < 8; ++nt) {
                float c0 = acc1[nt][0], c1 = acc1[nt][1], c2 = acc1[nt][2], c3 = acc1[nt][3];
                uint32_t p0 = bf2u(__float22bfloat162_rn(make_float2(c0 * c0, c1 * c1)));
                uint32_t p1 = bf2u(__float22bfloat162_rn(make_float2(c2 * c2, c3 * c3)));
                uint32_t koff = (uint32_t)((nt * 8 + hc2) * 2);
                sts32(ht + swz((uint32_t)((mh * 16 + hr) * 128) + koff), p0);
                sts32(ht + swz((uint32_t)((mh * 16 + hr + 8) * 128) + koff), p1);
            }
        }
        __syncthreads();

        // ---- issue W chunks 0,1 (both buffers free) ----
        if (tid == 0) {
            #pragma unroll
            for (int c = 0; c < 2; ++c) {
                uint32_t fb = c ? FB1 : FB0;
                mb_expect(fb, 65536u);
                bulkcp(BUF + c * 65536u, g_Wb + c * 65536, 65536u, fb);
            }
        }

        // ===== GEMM2: Gamma = h2 @ W^T in 8 n-chunks of 128, fused update =====
        for (int nc2 = 0; nc2 < 8; ++nc2) {
            const int s = nc2 & 1;
            float acc2[4][4];
            #pragma unroll
            for (int t = 0; t < 4; ++t)
                #pragma unroll
                for (int j = 0; j < 4; ++j) acc2[t][j] = 0.f;

            mb_wait(s ? FB1 : FB0, s ? ph1 : ph0);
            if (s) ph1 ^= 1; else ph0 ^= 1;
            const uint32_t Wc = BUF + (uint32_t)s * 65536u;
            #pragma unroll
            for (int kt = 0; kt < 4; ++kt) {
                const uint32_t At = H2 + (uint32_t)kt * 4096u;
                const uint32_t Bt = Wc + (uint32_t)kt * 16384u;
                #pragma unroll
                for (int ks = 0; ks < 4; ++ks) {
                    uint32_t a[4];
                    ldsm4(a, At + swz(arow + ks * 32));
                    #pragma unroll
                    for (int ntp = 0; ntp < 2; ++ntp) {
                        uint32_t b[4];
                        ldsm4(b, Bt + swz(brow + (uint32_t)((q * 32 + ntp * 16) * 128) + ks * 32));
                        mma16816(acc2[2 * ntp],     a, b);
                        mma16816(acc2[2 * ntp + 1], a, b + 2);
                    }
                }
            }
            __syncthreads();                 // W buf consumed + prior elementwise done (sGamma safe)
            if (nc2 + 2 < 8 && tid == 0) {
                uint32_t fb = s ? FB1 : FB0;
                mb_expect(fb, 65536u);
                bulkcp(BUF + (uint32_t)s * 65536u, g_Wb + (nc2 + 2) * 65536, 65536u, fb);
            }

            // store Gamma chunk to smem (f32, padded stride 132)
            #pragma unroll
            for (int nt = 0; nt < 4; ++nt) {
                int col = q * 32 + nt * 8 + hc2;
                *(float2*)(SGf + (mh * 16 + hr) * 132 + col)     = make_float2(acc2[nt][0], acc2[nt][1]);
                *(float2*)(SGf + (mh * 16 + hr + 8) * 132 + col) = make_float2(acc2[nt][2], acc2[nt][3]);
            }
            __syncthreads();

            // fused elementwise over this 128-d chunk (coalesced)
            const float* SGrow = SGf + er * 132;
            #pragma unroll
            for (int i = 0; i < 4; ++i) {
                const int dl = el + i * 32;
                const int d = nc2 * 128 + dl;
                float4 g4 = *(const float4*)(SGrow + dl);
                float4 f4 = *(const float4*)(force + grow + d);
                float4 v4 = *(const float4*)(vsrc + grow + d);
                float4 vn;
                vn.x = v4.x + dcoef * (f4.x - g4.x);
                vn.y = v4.y + dcoef * (f4.y - g4.y);
                vn.z = v4.z + dcoef * (f4.z - g4.z);
                vn.w = v4.w + dcoef * (f4.w - g4.w);
                *(float4*)(g_vf + grow + d) = vn;

                const int kc = d >> 6;
                uint2 pp;
                pp.x = bf2u(__float22bfloat162_rn(make_float2(vn.x, vn.y)));
                pp.y = bf2u(__float22bfloat162_rn(make_float2(vn.z, vn.w)));
                *(uint2*)(vbw + kc * 4096 + swz((uint32_t)(er * 128 + (d & 63) * 2))) = pp;

                float4* ox = (float4*)(out + grow + d);
                if (step == 0) {
                    float4 t;
                    t.x = K_C1f * v4.x + K_C2f * vn.x; t.y = K_C1f * v4.y + K_C2f * vn.y;
                    t.z = K_C1f * v4.z + K_C2f * vn.z; t.w = K_C1f * v4.w + K_C2f * vn.w;
                    *ox = t;
                } else if (step == 1) {
                    float4 t = *ox;
                    t.x += K_C2f * vn.x; t.y += K_C2f * vn.y;
                    t.z += K_C2f * vn.z; t.w += K_C2f * vn.w;
                    *ox = t;
                } else {
                    float4 t = *ox;
                    float4 x4 = *(const float4*)(x + grow + d);
                    t.x = x4.x + K_DT * (t.x + K_C1f * vn.x);
                    t.y = x4.y + K_DT * (t.y + K_C1f * vn.y);
                    t.z = x4.z + K_DT * (t.z + K_C1f * vn.z);
                    t.w = x4.w + K_DT * (t.w + K_C1f * vn.w);
                    *ox = t;
                    *(float4*)(out + (size_t)BB * DD + grow + d) = vn;
                }
            }
        }
        __syncthreads();   // elementwise done before next step's fence + reissue
    }
}

extern "C" void kernel_launch(void* const* d_in, const int* in_sizes, int n_in,
                              void* d_out, int out_size)
{
    const float* x     = (const float*)d_in[0];
    const float* v     = (const float*)d_in[1];
    const float* force = (const float*)d_in[2];
    const float* U     = (const float*)d_in[3];
    const float* W     = (const float*)d_in[4];
    float* out = (float*)d_out;

    const int smem_bytes = 165504;
    cudaFuncSetAttribute(yoshida_mma_kernel, cudaFuncAttributeMaxDynamicSharedMemorySize, smem_bytes);

    prep_uw_kernel<<<1024, 256>>>(U, W);
    prep_v_kernel<<<8192, 256>>>(v);
    yoshida_mma_kernel<<<NCTA, NTHR, smem_bytes>>>(x, v, force, out);
}